// round 8
// baseline (speedup 1.0000x reference)
#include <cuda_runtime.h>
#include <cuda_bf16.h>
#include <cstdint>

#define D 128
#define DV 32          // D / 4 (float4)
#define EPS 1e-5f
#define NT 64          // nodes per MLP block
#define PA 136         // bf16 tile pitch (272B rows -> conflict-free LDSM)
#define PS 132         // f32 h2 tile pitch
#define MAXN 50000

// Device scratch (allocation-free rule: __device__ globals).
// g_agg4 is zero at module load (.bss) and re-zeroed by k_mlp after each use,
// so every launch (correctness run + every graph replay) sees zeros.
__device__ float4 g_agg4[(size_t)MAXN * DV];
__device__ float4 g_hln4[(size_t)MAXN * DV];
__device__ float  g_colsum[D];      // zeroed by k_prep each launch
__device__ float  g_colsumsq[D];
// Pre-packed weights in B-fragment register order:
// [kt(8)][nsub(16)][lane(32)] -> uint4{bhi0,bhi1,blo0,blo1}
__device__ uint4  g_w1p[4096];
__device__ uint4  g_w2p[4096];

// SMEM layout for k_mlp (A region reused for H, then sS, then partials)
#define OFF_ALO 17408            // hi at 0, lo at 17408
#define SMEM_TOTAL 34816

// ---------------------------------------------------------------------------
// helpers
// ---------------------------------------------------------------------------
__device__ __forceinline__ uint32_t smem_u32(const void* p) {
    return (uint32_t)__cvta_generic_to_shared(p);
}

__device__ __forceinline__ void ldsm_x4(uint32_t* r, uint32_t addr) {
    asm volatile("ldmatrix.sync.aligned.m8n8.x4.shared.b16 {%0,%1,%2,%3}, [%4];"
                 : "=r"(r[0]), "=r"(r[1]), "=r"(r[2]), "=r"(r[3]) : "r"(addr));
}

__device__ __forceinline__ void mma16816(float* d, const uint32_t* a,
                                         const uint32_t* b) {
    asm volatile(
        "mma.sync.aligned.m16n8k16.row.col.f32.bf16.bf16.f32 "
        "{%0,%1,%2,%3}, {%4,%5,%6,%7}, {%8,%9}, {%0,%1,%2,%3};"
        : "+f"(d[0]), "+f"(d[1]), "+f"(d[2]), "+f"(d[3])
        : "r"(a[0]), "r"(a[1]), "r"(a[2]), "r"(a[3]), "r"(b[0]), "r"(b[1]));
}

__device__ __forceinline__ uint32_t bf2_hi(float a, float b, float& ra, float& rb) {
    __nv_bfloat16 ha = __float2bfloat16_rn(a);
    __nv_bfloat16 hb = __float2bfloat16_rn(b);
    ra = a - __bfloat162float(ha);
    rb = b - __bfloat162float(hb);
    __nv_bfloat162 h; h.x = ha; h.y = hb;
    return *(uint32_t*)&h;
}
__device__ __forceinline__ uint32_t bf2(float a, float b) {
    __nv_bfloat162 h; h.x = __float2bfloat16_rn(a); h.y = __float2bfloat16_rn(b);
    return *(uint32_t*)&h;
}

// ---------------------------------------------------------------------------
// K1: scatter-add messages. eh is streamed (read-once) via __ldcs to keep
// L1 capacity for the nh gather. edge_index is int32.
// ---------------------------------------------------------------------------
__global__ void k_scatter(const float* __restrict__ nh,
                          const float* __restrict__ eh,
                          const int* __restrict__ ei,
                          int E) {
    int gw   = (blockIdx.x * blockDim.x + threadIdx.x) >> 5;
    int lane = threadIdx.x & 31;
    if (gw >= E) return;
    int src = ei[gw];
    int dst = ei[E + gw];
    const float4* nh4 = (const float4*)(nh + (size_t)src * D);
    const float4* eh4 = (const float4*)(eh + (size_t)gw * D);
    float4 a = nh4[lane];
    float4 b = __ldcs(eh4 + lane);
    float4 v = make_float4(a.x + b.x, a.y + b.y, a.z + b.z, a.w + b.w);
    float* p = (float*)(g_agg4 + (size_t)dst * DV) + lane * 4;
    asm volatile("red.global.add.v4.f32 [%0], {%1, %2, %3, %4};"
                 :: "l"(p), "f"(v.x), "f"(v.y), "f"(v.z), "f"(v.w)
                 : "memory");
}

// ---------------------------------------------------------------------------
// Kp: pack W1/W2 into bf16 hi/lo B-fragment order (4096 threads).
// Block 0 also zeroes the GraphNorm stat accumulators for this launch
// (previous launch's k_final has already consumed them — stream order).
// ---------------------------------------------------------------------------
__global__ void k_prep(const float* __restrict__ w1, const float* __restrict__ w2) {
    int idx = blockIdx.x * blockDim.x + threadIdx.x;
    if (blockIdx.x == 0 && threadIdx.x < D) {
        g_colsum[threadIdx.x] = 0.f;
        g_colsumsq[threadIdx.x] = 0.f;
    }
    if (idx >= 4096) return;
    int lane = idx & 31;
    int nsub = (idx >> 5) & 15;
    int kt   = idx >> 9;
    int k0 = kt * 16 + (lane & 3) * 2;
    int n  = nsub * 8 + (lane >> 2);

    {
        float a0 = w1[(k0    ) * D + n], a1 = w1[(k0 + 1) * D + n];
        float a2 = w1[(k0 + 8) * D + n], a3 = w1[(k0 + 9) * D + n];
        float r0, r1, r2, r3;
        uint4 q;
        q.x = bf2_hi(a0, a1, r0, r1);
        q.y = bf2_hi(a2, a3, r2, r3);
        q.z = bf2(r0, r1);
        q.w = bf2(r2, r3);
        g_w1p[idx] = q;
    }
    {
        float a0 = w2[(k0    ) * D + n], a1 = w2[(k0 + 1) * D + n];
        float a2 = w2[(k0 + 8) * D + n], a3 = w2[(k0 + 9) * D + n];
        float r0, r1, r2, r3;
        uint4 q;
        q.x = bf2_hi(a0, a1, r0, r1);
        q.y = bf2_hi(a2, a3, r2, r3);
        q.z = bf2(r0, r1);
        q.w = bf2(r2, r3);
        g_w2p[idx] = q;
    }
}

// ---------------------------------------------------------------------------
// K2: tensor-core MLP, NT=64 nodes/block, 8 warps.
// Warp w: mh = w & 1 (32-row half), nq = w >> 1 (32-col quarter).
// Warp tile: m32 x n32 (acc[2][16]).
// After consuming its agg rows, each loader thread re-zeroes them in global
// (replaces the k_zero kernel; keeps every launch deterministic).
// ---------------------------------------------------------------------------
__global__ void k_mlp(const float* __restrict__ b1, const float* __restrict__ b2,
                      const float* __restrict__ lng, const float* __restrict__ lnb,
                      int N) {
    extern __shared__ char sb[];
    __nv_bfloat16* sHi = (__nv_bfloat16*)(sb);
    float*         sS  = (float*)(sb);
    float*         sPartS = (float*)(sb);
    float*         sPartQ = (float*)(sb + 4096);

    const int t    = threadIdx.x;
    const int lane = t & 31;
    const int w    = t >> 5;
    const int nodeBase = blockIdx.x * NT;

    // ---- load agg tile (64 nodes), split to bf16 hi/lo, then zero source ----
    {
        int n  = t >> 2;             // 0..63
        int k0 = (t & 3) * 32;       // 0,32,64,96
        int gn = nodeBase + n;
        __nv_bfloat16* rowHi = sHi + n * PA;
        #pragma unroll
        for (int i = 0; i < 8; ++i) {
            float4 v = make_float4(0.f, 0.f, 0.f, 0.f);
            if (gn < N) {
                float4* gp = &g_agg4[(size_t)gn * DV + (k0 >> 2) + i];
                v = *gp;
                __stcs(gp, make_float4(0.f, 0.f, 0.f, 0.f));  // re-zero for next launch
            }
            int kk = k0 + i * 4;
            float rx, ry, rz, rw;
            uint32_t h0 = bf2_hi(v.x, v.y, rx, ry);
            uint32_t h1 = bf2_hi(v.z, v.w, rz, rw);
            *(uint32_t*)((char*)(rowHi + kk))               = h0;
            *(uint32_t*)((char*)(rowHi + kk + 2))           = h1;
            *(uint32_t*)((char*)(rowHi + kk) + OFF_ALO)     = bf2(rx, ry);
            *(uint32_t*)((char*)(rowHi + kk + 2) + OFF_ALO) = bf2(rz, rw);
        }
    }
    __syncthreads();

    const int mh = w & 1;            // 32-row half
    const int nq = w >> 1;           // 32-col quarter
    const uint32_t aB0 = smem_u32(sHi + (mh * 32 + (lane & 15)) * PA) + (lane >> 4) * 16;
    const uint32_t aB1 = aB0 + 16 * PA * 2;   // +16 rows

    float acc[32];
    #pragma unroll
    for (int i = 0; i < 32; ++i) acc[i] = 0.f;

    // ---- layer 1: h1 = relu(agg @ W1 + b1) ----
    #pragma unroll
    for (int kt = 0; kt < 8; ++kt) {
        uint32_t a0h[4], a0l[4], a1h[4], a1l[4];
        ldsm_x4(a0h, aB0 + kt * 32);
        ldsm_x4(a0l, aB0 + OFF_ALO + kt * 32);
        ldsm_x4(a1h, aB1 + kt * 32);
        ldsm_x4(a1l, aB1 + OFF_ALO + kt * 32);
        #pragma unroll
        for (int s = 0; s < 4; ++s) {
            uint4 q = g_w1p[(kt * 16 + nq * 4 + s) * 32 + lane];
            mma16816(acc + 4 * s,      a0h, &q.x);
            mma16816(acc + 4 * s,      a0h, &q.z);
            mma16816(acc + 4 * s,      a0l, &q.x);
            mma16816(acc + 16 + 4 * s, a1h, &q.x);
            mma16816(acc + 16 + 4 * s, a1h, &q.z);
            mma16816(acc + 16 + 4 * s, a1l, &q.x);
        }
    }
    __syncthreads();                 // everyone done reading A -> overwrite with H
    #pragma unroll
    for (int m = 0; m < 2; ++m) {
        #pragma unroll
        for (int s = 0; s < 4; ++s) {
            int cb = nq * 32 + s * 8 + (lane & 3) * 2;
            int r0 = mh * 32 + m * 16 + (lane >> 2);
            float2 bb = *(const float2*)(b1 + cb);
            float v00 = fmaxf(acc[16*m + 4*s + 0] + bb.x, 0.f);
            float v01 = fmaxf(acc[16*m + 4*s + 1] + bb.y, 0.f);
            float v10 = fmaxf(acc[16*m + 4*s + 2] + bb.x, 0.f);
            float v11 = fmaxf(acc[16*m + 4*s + 3] + bb.y, 0.f);
            float rx, ry;
            char* p0 = (char*)(sHi + r0 * PA + cb);
            char* p1 = (char*)(sHi + (r0 + 8) * PA + cb);
            uint32_t h;
            h = bf2_hi(v00, v01, rx, ry);
            *(uint32_t*)p0 = h; *(uint32_t*)(p0 + OFF_ALO) = bf2(rx, ry);
            h = bf2_hi(v10, v11, rx, ry);
            *(uint32_t*)p1 = h; *(uint32_t*)(p1 + OFF_ALO) = bf2(rx, ry);
        }
    }
    __syncthreads();

    #pragma unroll
    for (int i = 0; i < 32; ++i) acc[i] = 0.f;

    // ---- layer 2: h2 = h1 @ W2 + b2 (H lives in the A region) ----
    #pragma unroll
    for (int kt = 0; kt < 8; ++kt) {
        uint32_t a0h[4], a0l[4], a1h[4], a1l[4];
        ldsm_x4(a0h, aB0 + kt * 32);
        ldsm_x4(a0l, aB0 + OFF_ALO + kt * 32);
        ldsm_x4(a1h, aB1 + kt * 32);
        ldsm_x4(a1l, aB1 + OFF_ALO + kt * 32);
        #pragma unroll
        for (int s = 0; s < 4; ++s) {
            uint4 q = g_w2p[(kt * 16 + nq * 4 + s) * 32 + lane];
            mma16816(acc + 4 * s,      a0h, &q.x);
            mma16816(acc + 4 * s,      a0h, &q.z);
            mma16816(acc + 4 * s,      a0l, &q.x);
            mma16816(acc + 16 + 4 * s, a1h, &q.x);
            mma16816(acc + 16 + 4 * s, a1h, &q.z);
            mma16816(acc + 16 + 4 * s, a1l, &q.x);
        }
    }
    __syncthreads();                 // H dead -> overwrite with sS
    #pragma unroll
    for (int m = 0; m < 2; ++m) {
        #pragma unroll
        for (int s = 0; s < 4; ++s) {
            int cb = nq * 32 + s * 8 + (lane & 3) * 2;
            int r0 = mh * 32 + m * 16 + (lane >> 2);
            float2 bb = *(const float2*)(b2 + cb);
            *(float2*)(sS + r0 * PS + cb)       = make_float2(acc[16*m + 4*s + 0] + bb.x,
                                                              acc[16*m + 4*s + 1] + bb.y);
            *(float2*)(sS + (r0 + 8) * PS + cb) = make_float2(acc[16*m + 4*s + 2] + bb.x,
                                                              acc[16*m + 4*s + 3] + bb.y);
        }
    }
    __syncthreads();

    // ---- LayerNorm per node (warp per node, 8 nodes/warp) + column partials ----
    float colS[4] = {0.f, 0.f, 0.f, 0.f};
    float colQ[4] = {0.f, 0.f, 0.f, 0.f};

    #pragma unroll
    for (int r = 0; r < 8; ++r) {
        int n  = w + r * 8;          // 0..63
        int gn = nodeBase + n;
        float v0 = sS[n * PS + lane];
        float v1 = sS[n * PS + lane + 32];
        float v2 = sS[n * PS + lane + 64];
        float v3 = sS[n * PS + lane + 96];
        float s = v0 + v1 + v2 + v3;
        float q = v0*v0 + v1*v1 + v2*v2 + v3*v3;
        #pragma unroll
        for (int o = 16; o; o >>= 1) {
            s += __shfl_xor_sync(0xFFFFFFFFu, s, o);
            q += __shfl_xor_sync(0xFFFFFFFFu, q, o);
        }
        float mu  = s * (1.f / 128.f);
        float var = q * (1.f / 128.f) - mu * mu;
        float inv = rsqrtf(var + EPS);
        if (gn < N) {
            float y0 = (v0 - mu) * inv * lng[lane]      + lnb[lane];
            float y1 = (v1 - mu) * inv * lng[lane + 32] + lnb[lane + 32];
            float y2 = (v2 - mu) * inv * lng[lane + 64] + lnb[lane + 64];
            float y3 = (v3 - mu) * inv * lng[lane + 96] + lnb[lane + 96];
            float* hp = (float*)(g_hln4 + (size_t)gn * DV);
            hp[lane]      = y0;
            hp[lane + 32] = y1;
            hp[lane + 64] = y2;
            hp[lane + 96] = y3;
            colS[0] += y0; colQ[0] += y0 * y0;
            colS[1] += y1; colQ[1] += y1 * y1;
            colS[2] += y2; colQ[2] += y2 * y2;
            colS[3] += y3; colQ[3] += y3 * y3;
        }
    }
    __syncthreads();                 // sS dead -> partials
    #pragma unroll
    for (int qq = 0; qq < 4; ++qq) {
        sPartS[w * D + lane + 32 * qq] = colS[qq];
        sPartQ[w * D + lane + 32 * qq] = colQ[qq];
    }
    __syncthreads();
    if (t < D) {
        float s = 0.f, q = 0.f;
        #pragma unroll
        for (int w8 = 0; w8 < 8; ++w8) {
            s += sPartS[w8 * D + t];
            q += sPartQ[w8 * D + t];
        }
        atomicAdd(&g_colsum[t], s);
        atomicAdd(&g_colsumsq[t], q);
    }
}

// ---------------------------------------------------------------------------
// K4: out = relu((hln - ms*gmu) * mul + gn_b) + node_hidden
// GraphNorm finalize recomputed per block from L2-resident accumulators.
// ---------------------------------------------------------------------------
__global__ void k_final(const float* __restrict__ nh,
                        const float* __restrict__ gnw,
                        const float* __restrict__ gnb,
                        const float* __restrict__ gnms,
                        float invN,
                        float* __restrict__ out,
                        int total4) {
    __shared__ float sMul[D], sSub[D], sB[D];
    int t = threadIdx.x;
    if (t < D) {
        float gmu = g_colsum[t] * invN;
        float e2  = g_colsumsq[t] * invN;
        float ms  = gnms[t];
        float gvar = e2 - 2.f * ms * gmu * gmu + ms * ms * gmu * gmu;
        sMul[t] = rsqrtf(gvar + EPS) * gnw[t];
        sSub[t] = ms * gmu;
        sB[t]   = gnb[t];
    }
    __syncthreads();
    int i = blockIdx.x * blockDim.x + t;
    if (i >= total4) return;
    int c4 = (i & (DV - 1)) * 4;
    float4 h = g_hln4[i];
    float4 x = ((const float4*)nh)[i];
    float4 o;
    o.x = fmaxf((h.x - sSub[c4 + 0]) * sMul[c4 + 0] + sB[c4 + 0], 0.f) + x.x;
    o.y = fmaxf((h.y - sSub[c4 + 1]) * sMul[c4 + 1] + sB[c4 + 1], 0.f) + x.y;
    o.z = fmaxf((h.z - sSub[c4 + 2]) * sMul[c4 + 2] + sB[c4 + 2], 0.f) + x.z;
    o.w = fmaxf((h.w - sSub[c4 + 3]) * sMul[c4 + 3] + sB[c4 + 3], 0.f) + x.w;
    ((float4*)out)[i] = o;
}

// ---------------------------------------------------------------------------
extern "C" void kernel_launch(void* const* d_in, const int* in_sizes, int n_in,
                              void* d_out, int out_size) {
    const float* nh   = (const float*)d_in[0];
    const float* eh   = (const float*)d_in[1];
    const float* w1   = (const float*)d_in[2];
    const float* b1   = (const float*)d_in[3];
    const float* w2   = (const float*)d_in[4];
    const float* b2   = (const float*)d_in[5];
    const float* lng  = (const float*)d_in[6];
    const float* lnb  = (const float*)d_in[7];
    const float* gnw  = (const float*)d_in[8];
    const float* gnb  = (const float*)d_in[9];
    const float* gnms = (const float*)d_in[10];
    const int*   ei   = (const int*)d_in[11];

    int N = in_sizes[0] / D;
    int E = in_sizes[1] / D;
    int total4 = N * DV;

    cudaFuncSetAttribute(k_mlp, cudaFuncAttributeMaxDynamicSharedMemorySize, SMEM_TOTAL);

    k_prep<<<16, 256>>>(w1, w2);
    k_scatter<<<(E + 7) / 8, 256>>>(nh, eh, ei, E);
    k_mlp<<<(N + NT - 1) / NT, 256, SMEM_TOTAL>>>(b1, b2, lng, lnb, N);
    k_final<<<(total4 + 255) / 256, 256>>>(nh, gnw, gnb, gnms, 1.f / (float)N,
                                           (float*)d_out, total4);
}

// round 9
// speedup vs baseline: 1.3535x; 1.3535x over previous
#include <cuda_runtime.h>
#include <cuda_bf16.h>
#include <cstdint>

#define D 128
#define DV 32          // D / 4 (float4)
#define EPS 1e-5f
#define NT 64          // nodes per MLP block
#define PA 136         // bf16 tile pitch (272B rows -> conflict-free LDSM)
#define PS 132         // f32 h2 tile pitch
#define MAXN 50000

// Device scratch (allocation-free rule: __device__ globals)
__device__ float4 g_agg4[(size_t)MAXN * DV];   // aggregated messages [N][D]
__device__ float4 g_hln4[(size_t)MAXN * DV];   // post-LayerNorm h    [N][D]
__device__ float  g_colsum[D];
__device__ float  g_colsumsq[D];
// Pre-packed weights in B-fragment register order:
// [kt(8)][nsub(16)][lane(32)] -> uint4{bhi0,bhi1,blo0,blo1}
__device__ uint4  g_w1p[4096];
__device__ uint4  g_w2p[4096];

// SMEM layout for k_mlp (A region reused for H, then sS, then partials)
#define OFF_ALO 17408            // hi at 0, lo at 17408
#define SMEM_TOTAL 34816

// ---------------------------------------------------------------------------
// helpers
// ---------------------------------------------------------------------------
__device__ __forceinline__ uint32_t smem_u32(const void* p) {
    return (uint32_t)__cvta_generic_to_shared(p);
}

__device__ __forceinline__ void ldsm_x4(uint32_t* r, uint32_t addr) {
    asm volatile("ldmatrix.sync.aligned.m8n8.x4.shared.b16 {%0,%1,%2,%3}, [%4];"
                 : "=r"(r[0]), "=r"(r[1]), "=r"(r[2]), "=r"(r[3]) : "r"(addr));
}

__device__ __forceinline__ void mma16816(float* d, const uint32_t* a,
                                         const uint32_t* b) {
    asm volatile(
        "mma.sync.aligned.m16n8k16.row.col.f32.bf16.bf16.f32 "
        "{%0,%1,%2,%3}, {%4,%5,%6,%7}, {%8,%9}, {%0,%1,%2,%3};"
        : "+f"(d[0]), "+f"(d[1]), "+f"(d[2]), "+f"(d[3])
        : "r"(a[0]), "r"(a[1]), "r"(a[2]), "r"(a[3]), "r"(b[0]), "r"(b[1]));
}

__device__ __forceinline__ uint32_t bf2_hi(float a, float b, float& ra, float& rb) {
    __nv_bfloat16 ha = __float2bfloat16_rn(a);
    __nv_bfloat16 hb = __float2bfloat16_rn(b);
    ra = a - __bfloat162float(ha);
    rb = b - __bfloat162float(hb);
    __nv_bfloat162 h; h.x = ha; h.y = hb;
    return *(uint32_t*)&h;
}
__device__ __forceinline__ uint32_t bf2(float a, float b) {
    __nv_bfloat162 h; h.x = __float2bfloat16_rn(a); h.y = __float2bfloat16_rn(b);
    return *(uint32_t*)&h;
}

// ---------------------------------------------------------------------------
// K0: zero agg (L2-warm for the scatter atomics) + stats, and pack weights.
// grid = ceil(total4/256); the first 16 blocks (idx < 4096) also pack W1/W2.
// ---------------------------------------------------------------------------
__global__ void k_pre(const float* __restrict__ w1, const float* __restrict__ w2,
                      int total4) {
    int idx = blockIdx.x * blockDim.x + threadIdx.x;
    if (idx < total4) g_agg4[idx] = make_float4(0.f, 0.f, 0.f, 0.f);
    if (idx < D) { g_colsum[idx] = 0.f; g_colsumsq[idx] = 0.f; }
    if (idx >= 4096) return;

    int lane = idx & 31;
    int nsub = (idx >> 5) & 15;
    int kt   = idx >> 9;
    int k0 = kt * 16 + (lane & 3) * 2;
    int n  = nsub * 8 + (lane >> 2);

    {
        float a0 = w1[(k0    ) * D + n], a1 = w1[(k0 + 1) * D + n];
        float a2 = w1[(k0 + 8) * D + n], a3 = w1[(k0 + 9) * D + n];
        float r0, r1, r2, r3;
        uint4 q;
        q.x = bf2_hi(a0, a1, r0, r1);
        q.y = bf2_hi(a2, a3, r2, r3);
        q.z = bf2(r0, r1);
        q.w = bf2(r2, r3);
        g_w1p[idx] = q;
    }
    {
        float a0 = w2[(k0    ) * D + n], a1 = w2[(k0 + 1) * D + n];
        float a2 = w2[(k0 + 8) * D + n], a3 = w2[(k0 + 9) * D + n];
        float r0, r1, r2, r3;
        uint4 q;
        q.x = bf2_hi(a0, a1, r0, r1);
        q.y = bf2_hi(a2, a3, r2, r3);
        q.z = bf2(r0, r1);
        q.w = bf2(r2, r3);
        g_w2p[idx] = q;
    }
}

// ---------------------------------------------------------------------------
// K1: scatter-add messages (proven R3/R6 form). edge_index is int32.
// ---------------------------------------------------------------------------
__global__ void k_scatter(const float* __restrict__ nh,
                          const float* __restrict__ eh,
                          const int* __restrict__ ei,
                          int E) {
    int gw   = (blockIdx.x * blockDim.x + threadIdx.x) >> 5;
    int lane = threadIdx.x & 31;
    if (gw >= E) return;
    int src = ei[gw];
    int dst = ei[E + gw];
    const float4* nh4 = (const float4*)(nh + (size_t)src * D);
    const float4* eh4 = (const float4*)(eh + (size_t)gw * D);
    float4 a = nh4[lane];
    float4 b = eh4[lane];
    float4 v = make_float4(a.x + b.x, a.y + b.y, a.z + b.z, a.w + b.w);
    float* p = (float*)(g_agg4 + (size_t)dst * DV) + lane * 4;
    asm volatile("red.global.add.v4.f32 [%0], {%1, %2, %3, %4};"
                 :: "l"(p), "f"(v.x), "f"(v.y), "f"(v.z), "f"(v.w)
                 : "memory");
}

// ---------------------------------------------------------------------------
// K2: tensor-core MLP, NT=64 nodes/block, 8 warps (R6 proven form).
// Warp w: mh = w & 1 (32-row half), nq = w >> 1 (32-col quarter).
// ---------------------------------------------------------------------------
__global__ void k_mlp(const float* __restrict__ b1, const float* __restrict__ b2,
                      const float* __restrict__ lng, const float* __restrict__ lnb,
                      int N) {
    extern __shared__ char sb[];
    __nv_bfloat16* sHi = (__nv_bfloat16*)(sb);
    float*         sS  = (float*)(sb);
    float*         sPartS = (float*)(sb);
    float*         sPartQ = (float*)(sb + 4096);

    const int t    = threadIdx.x;
    const int lane = t & 31;
    const int w    = t >> 5;
    const int nodeBase = blockIdx.x * NT;

    // ---- load agg tile (64 nodes), split to bf16 hi/lo ----
    {
        int n  = t >> 2;             // 0..63
        int k0 = (t & 3) * 32;       // 0,32,64,96
        int gn = nodeBase + n;
        __nv_bfloat16* rowHi = sHi + n * PA;
        #pragma unroll
        for (int i = 0; i < 8; ++i) {
            float4 v = make_float4(0.f, 0.f, 0.f, 0.f);
            if (gn < N) v = g_agg4[(size_t)gn * DV + (k0 >> 2) + i];
            int kk = k0 + i * 4;
            float rx, ry, rz, rw;
            uint32_t h0 = bf2_hi(v.x, v.y, rx, ry);
            uint32_t h1 = bf2_hi(v.z, v.w, rz, rw);
            *(uint32_t*)((char*)(rowHi + kk))               = h0;
            *(uint32_t*)((char*)(rowHi + kk + 2))           = h1;
            *(uint32_t*)((char*)(rowHi + kk) + OFF_ALO)     = bf2(rx, ry);
            *(uint32_t*)((char*)(rowHi + kk + 2) + OFF_ALO) = bf2(rz, rw);
        }
    }
    __syncthreads();

    const int mh = w & 1;            // 32-row half
    const int nq = w >> 1;           // 32-col quarter
    const uint32_t aB0 = smem_u32(sHi + (mh * 32 + (lane & 15)) * PA) + (lane >> 4) * 16;
    const uint32_t aB1 = aB0 + 16 * PA * 2;   // +16 rows

    float acc[32];
    #pragma unroll
    for (int i = 0; i < 32; ++i) acc[i] = 0.f;

    // ---- layer 1: h1 = relu(agg @ W1 + b1) ----
    #pragma unroll
    for (int kt = 0; kt < 8; ++kt) {
        uint32_t a0h[4], a0l[4], a1h[4], a1l[4];
        ldsm_x4(a0h, aB0 + kt * 32);
        ldsm_x4(a0l, aB0 + OFF_ALO + kt * 32);
        ldsm_x4(a1h, aB1 + kt * 32);
        ldsm_x4(a1l, aB1 + OFF_ALO + kt * 32);
        #pragma unroll
        for (int s = 0; s < 4; ++s) {
            uint4 q = g_w1p[(kt * 16 + nq * 4 + s) * 32 + lane];
            mma16816(acc + 4 * s,      a0h, &q.x);
            mma16816(acc + 4 * s,      a0h, &q.z);
            mma16816(acc + 4 * s,      a0l, &q.x);
            mma16816(acc + 16 + 4 * s, a1h, &q.x);
            mma16816(acc + 16 + 4 * s, a1h, &q.z);
            mma16816(acc + 16 + 4 * s, a1l, &q.x);
        }
    }
    __syncthreads();                 // everyone done reading A -> overwrite with H
    #pragma unroll
    for (int m = 0; m < 2; ++m) {
        #pragma unroll
        for (int s = 0; s < 4; ++s) {
            int cb = nq * 32 + s * 8 + (lane & 3) * 2;
            int r0 = mh * 32 + m * 16 + (lane >> 2);
            float2 bb = *(const float2*)(b1 + cb);
            float v00 = fmaxf(acc[16*m + 4*s + 0] + bb.x, 0.f);
            float v01 = fmaxf(acc[16*m + 4*s + 1] + bb.y, 0.f);
            float v10 = fmaxf(acc[16*m + 4*s + 2] + bb.x, 0.f);
            float v11 = fmaxf(acc[16*m + 4*s + 3] + bb.y, 0.f);
            float rx, ry;
            char* p0 = (char*)(sHi + r0 * PA + cb);
            char* p1 = (char*)(sHi + (r0 + 8) * PA + cb);
            uint32_t h;
            h = bf2_hi(v00, v01, rx, ry);
            *(uint32_t*)p0 = h; *(uint32_t*)(p0 + OFF_ALO) = bf2(rx, ry);
            h = bf2_hi(v10, v11, rx, ry);
            *(uint32_t*)p1 = h; *(uint32_t*)(p1 + OFF_ALO) = bf2(rx, ry);
        }
    }
    __syncthreads();

    #pragma unroll
    for (int i = 0; i < 32; ++i) acc[i] = 0.f;

    // ---- layer 2: h2 = h1 @ W2 + b2 (H lives in the A region) ----
    #pragma unroll
    for (int kt = 0; kt < 8; ++kt) {
        uint32_t a0h[4], a0l[4], a1h[4], a1l[4];
        ldsm_x4(a0h, aB0 + kt * 32);
        ldsm_x4(a0l, aB0 + OFF_ALO + kt * 32);
        ldsm_x4(a1h, aB1 + kt * 32);
        ldsm_x4(a1l, aB1 + OFF_ALO + kt * 32);
        #pragma unroll
        for (int s = 0; s < 4; ++s) {
            uint4 q = g_w2p[(kt * 16 + nq * 4 + s) * 32 + lane];
            mma16816(acc + 4 * s,      a0h, &q.x);
            mma16816(acc + 4 * s,      a0h, &q.z);
            mma16816(acc + 4 * s,      a0l, &q.x);
            mma16816(acc + 16 + 4 * s, a1h, &q.x);
            mma16816(acc + 16 + 4 * s, a1h, &q.z);
            mma16816(acc + 16 + 4 * s, a1l, &q.x);
        }
    }
    __syncthreads();                 // H dead -> overwrite with sS
    #pragma unroll
    for (int m = 0; m < 2; ++m) {
        #pragma unroll
        for (int s = 0; s < 4; ++s) {
            int cb = nq * 32 + s * 8 + (lane & 3) * 2;
            int r0 = mh * 32 + m * 16 + (lane >> 2);
            float2 bb = *(const float2*)(b2 + cb);
            *(float2*)(sS + r0 * PS + cb)       = make_float2(acc[16*m + 4*s + 0] + bb.x,
                                                              acc[16*m + 4*s + 1] + bb.y);
            *(float2*)(sS + (r0 + 8) * PS + cb) = make_float2(acc[16*m + 4*s + 2] + bb.x,
                                                              acc[16*m + 4*s + 3] + bb.y);
        }
    }
    __syncthreads();

    // ---- LayerNorm per node (warp per node, 8 nodes/warp) + column partials ----
    float colS[4] = {0.f, 0.f, 0.f, 0.f};
    float colQ[4] = {0.f, 0.f, 0.f, 0.f};

    #pragma unroll
    for (int r = 0; r < 8; ++r) {
        int n  = w + r * 8;          // 0..63
        int gn = nodeBase + n;
        float v0 = sS[n * PS + lane];
        float v1 = sS[n * PS + lane + 32];
        float v2 = sS[n * PS + lane + 64];
        float v3 = sS[n * PS + lane + 96];
        float s = v0 + v1 + v2 + v3;
        float q = v0*v0 + v1*v1 + v2*v2 + v3*v3;
        #pragma unroll
        for (int o = 16; o; o >>= 1) {
            s += __shfl_xor_sync(0xFFFFFFFFu, s, o);
            q += __shfl_xor_sync(0xFFFFFFFFu, q, o);
        }
        float mu  = s * (1.f / 128.f);
        float var = q * (1.f / 128.f) - mu * mu;
        float inv = rsqrtf(var + EPS);
        if (gn < N) {
            float y0 = (v0 - mu) * inv * lng[lane]      + lnb[lane];
            float y1 = (v1 - mu) * inv * lng[lane + 32] + lnb[lane + 32];
            float y2 = (v2 - mu) * inv * lng[lane + 64] + lnb[lane + 64];
            float y3 = (v3 - mu) * inv * lng[lane + 96] + lnb[lane + 96];
            float* hp = (float*)(g_hln4 + (size_t)gn * DV);
            hp[lane]      = y0;
            hp[lane + 32] = y1;
            hp[lane + 64] = y2;
            hp[lane + 96] = y3;
            colS[0] += y0; colQ[0] += y0 * y0;
            colS[1] += y1; colQ[1] += y1 * y1;
            colS[2] += y2; colQ[2] += y2 * y2;
            colS[3] += y3; colQ[3] += y3 * y3;
        }
    }
    __syncthreads();                 // sS dead -> partials
    #pragma unroll
    for (int qq = 0; qq < 4; ++qq) {
        sPartS[w * D + lane + 32 * qq] = colS[qq];
        sPartQ[w * D + lane + 32 * qq] = colQ[qq];
    }
    __syncthreads();
    if (t < D) {
        float s = 0.f, q = 0.f;
        #pragma unroll
        for (int w8 = 0; w8 < 8; ++w8) {
            s += sPartS[w8 * D + t];
            q += sPartQ[w8 * D + t];
        }
        atomicAdd(&g_colsum[t], s);
        atomicAdd(&g_colsumsq[t], q);
    }
}

// ---------------------------------------------------------------------------
// K4: out = relu((hln - ms*gmu) * mul + gn_b) + node_hidden.
// 2 float4 per thread for ILP; stats finalized per block from L2 accumulators.
// ---------------------------------------------------------------------------
__global__ void k_final(const float* __restrict__ nh,
                        const float* __restrict__ gnw,
                        const float* __restrict__ gnb,
                        const float* __restrict__ gnms,
                        float invN,
                        float* __restrict__ out,
                        int total4) {
    __shared__ float sMul[D], sSub[D], sB[D];
    int t = threadIdx.x;
    if (t < D) {
        float gmu = g_colsum[t] * invN;
        float e2  = g_colsumsq[t] * invN;
        float ms  = gnms[t];
        float gvar = e2 - 2.f * ms * gmu * gmu + ms * ms * gmu * gmu;
        sMul[t] = rsqrtf(gvar + EPS) * gnw[t];
        sSub[t] = ms * gmu;
        sB[t]   = gnb[t];
    }
    __syncthreads();
    int base = blockIdx.x * 512 + t;
    #pragma unroll
    for (int u = 0; u < 2; ++u) {
        int i = base + u * 256;
        if (i >= total4) break;
        int c4 = (i & (DV - 1)) * 4;
        float4 h = g_hln4[i];
        float4 x = ((const float4*)nh)[i];
        float4 o;
        o.x = fmaxf((h.x - sSub[c4 + 0]) * sMul[c4 + 0] + sB[c4 + 0], 0.f) + x.x;
        o.y = fmaxf((h.y - sSub[c4 + 1]) * sMul[c4 + 1] + sB[c4 + 1], 0.f) + x.y;
        o.z = fmaxf((h.z - sSub[c4 + 2]) * sMul[c4 + 2] + sB[c4 + 2], 0.f) + x.z;
        o.w = fmaxf((h.w - sSub[c4 + 3]) * sMul[c4 + 3] + sB[c4 + 3], 0.f) + x.w;
        ((float4*)out)[i] = o;
    }
}

// ---------------------------------------------------------------------------
extern "C" void kernel_launch(void* const* d_in, const int* in_sizes, int n_in,
                              void* d_out, int out_size) {
    const float* nh   = (const float*)d_in[0];
    const float* eh   = (const float*)d_in[1];
    const float* w1   = (const float*)d_in[2];
    const float* b1   = (const float*)d_in[3];
    const float* w2   = (const float*)d_in[4];
    const float* b2   = (const float*)d_in[5];
    const float* lng  = (const float*)d_in[6];
    const float* lnb  = (const float*)d_in[7];
    const float* gnw  = (const float*)d_in[8];
    const float* gnb  = (const float*)d_in[9];
    const float* gnms = (const float*)d_in[10];
    const int*   ei   = (const int*)d_in[11];

    int N = in_sizes[0] / D;
    int E = in_sizes[1] / D;
    int total4 = N * DV;

    cudaFuncSetAttribute(k_mlp, cudaFuncAttributeMaxDynamicSharedMemorySize, SMEM_TOTAL);

    k_pre<<<(total4 + 255) / 256, 256>>>(w1, w2, total4);
    k_scatter<<<(E + 7) / 8, 256>>>(nh, eh, ei, E);
    k_mlp<<<(N + NT - 1) / NT, 256, SMEM_TOTAL>>>(b1, b2, lng, lnb, N);
    k_final<<<(total4 + 511) / 512, 256>>>(nh, gnw, gnb, gnms, 1.f / (float)N,
                                           (float*)d_out, total4);
}

// round 10
// speedup vs baseline: 1.4283x; 1.0553x over previous
#include <cuda_runtime.h>
#include <cuda_bf16.h>
#include <cstdint>

#define D 128
#define DV 32          // D / 4 (float4)
#define EPS 1e-5f
#define NT 64          // nodes per MLP block
#define PA 136         // bf16 tile pitch (272B rows -> conflict-free LDSM)
#define PS 132         // f32 h2 tile pitch
#define MAXN 50000

// Device scratch (allocation-free rule: __device__ globals)
__device__ float4 g_agg4[(size_t)MAXN * DV];   // aggregated messages [N][D]
__device__ float4 g_hln4[(size_t)MAXN * DV];   // post-LayerNorm h    [N][D]
__device__ float  g_colsum[D];
__device__ float  g_colsumsq[D];
// Pre-packed weights in B-fragment register order:
// [kt(8)][nsub(16)][lane(32)] -> uint4{bhi0,bhi1,blo0,blo1}
__device__ uint4  g_w1p[4096];
__device__ uint4  g_w2p[4096];

// SMEM layout for k_mlp (A region reused for H, then sS, then partials)
#define OFF_ALO 17408            // hi at 0, lo at 17408
#define SMEM_TOTAL 34816

// ---------------------------------------------------------------------------
// helpers
// ---------------------------------------------------------------------------
__device__ __forceinline__ uint32_t smem_u32(const void* p) {
    return (uint32_t)__cvta_generic_to_shared(p);
}

__device__ __forceinline__ void ldsm_x4(uint32_t* r, uint32_t addr) {
    asm volatile("ldmatrix.sync.aligned.m8n8.x4.shared.b16 {%0,%1,%2,%3}, [%4];"
                 : "=r"(r[0]), "=r"(r[1]), "=r"(r[2]), "=r"(r[3]) : "r"(addr));
}

__device__ __forceinline__ void mma16816(float* d, const uint32_t* a,
                                         const uint32_t* b) {
    asm volatile(
        "mma.sync.aligned.m16n8k16.row.col.f32.bf16.bf16.f32 "
        "{%0,%1,%2,%3}, {%4,%5,%6,%7}, {%8,%9}, {%0,%1,%2,%3};"
        : "+f"(d[0]), "+f"(d[1]), "+f"(d[2]), "+f"(d[3])
        : "r"(a[0]), "r"(a[1]), "r"(a[2]), "r"(a[3]), "r"(b[0]), "r"(b[1]));
}

__device__ __forceinline__ uint32_t bf2_hi(float a, float b, float& ra, float& rb) {
    __nv_bfloat16 ha = __float2bfloat16_rn(a);
    __nv_bfloat16 hb = __float2bfloat16_rn(b);
    ra = a - __bfloat162float(ha);
    rb = b - __bfloat162float(hb);
    __nv_bfloat162 h; h.x = ha; h.y = hb;
    return *(uint32_t*)&h;
}
__device__ __forceinline__ uint32_t bf2(float a, float b) {
    __nv_bfloat162 h; h.x = __float2bfloat16_rn(a); h.y = __float2bfloat16_rn(b);
    return *(uint32_t*)&h;
}

// ---------------------------------------------------------------------------
// K0: zero agg (L2-warm for the scatter atomics) + stats, pack weights.
// 4 float4 per thread. grid = ceil(total4/1024); first 16 blocks pack W1/W2.
// ---------------------------------------------------------------------------
__global__ void k_pre(const float* __restrict__ w1, const float* __restrict__ w2,
                      int total4) {
    int idx = blockIdx.x * blockDim.x + threadIdx.x;
    int base = blockIdx.x * 1024 + threadIdx.x;
    #pragma unroll
    for (int u = 0; u < 4; ++u) {
        int i = base + u * 256;
        if (i < total4) g_agg4[i] = make_float4(0.f, 0.f, 0.f, 0.f);
    }
    if (idx < D) { g_colsum[idx] = 0.f; g_colsumsq[idx] = 0.f; }
    if (idx >= 4096) return;

    int lane = idx & 31;
    int nsub = (idx >> 5) & 15;
    int kt   = idx >> 9;
    int k0 = kt * 16 + (lane & 3) * 2;
    int n  = nsub * 8 + (lane >> 2);

    {
        float a0 = w1[(k0    ) * D + n], a1 = w1[(k0 + 1) * D + n];
        float a2 = w1[(k0 + 8) * D + n], a3 = w1[(k0 + 9) * D + n];
        float r0, r1, r2, r3;
        uint4 q;
        q.x = bf2_hi(a0, a1, r0, r1);
        q.y = bf2_hi(a2, a3, r2, r3);
        q.z = bf2(r0, r1);
        q.w = bf2(r2, r3);
        g_w1p[idx] = q;
    }
    {
        float a0 = w2[(k0    ) * D + n], a1 = w2[(k0 + 1) * D + n];
        float a2 = w2[(k0 + 8) * D + n], a3 = w2[(k0 + 9) * D + n];
        float r0, r1, r2, r3;
        uint4 q;
        q.x = bf2_hi(a0, a1, r0, r1);
        q.y = bf2_hi(a2, a3, r2, r3);
        q.z = bf2(r0, r1);
        q.w = bf2(r2, r3);
        g_w2p[idx] = q;
    }
}

// ---------------------------------------------------------------------------
// K1: scatter-add messages. eh streamed via __ldcs (read-once, evict-first);
// nh gather stays default-cached (hot 25.6MB table). edge_index is int32.
// ---------------------------------------------------------------------------
__global__ void k_scatter(const float* __restrict__ nh,
                          const float* __restrict__ eh,
                          const int* __restrict__ ei,
                          int E) {
    int gw   = (blockIdx.x * blockDim.x + threadIdx.x) >> 5;
    int lane = threadIdx.x & 31;
    if (gw >= E) return;
    int src = ei[gw];
    int dst = ei[E + gw];
    const float4* nh4 = (const float4*)(nh + (size_t)src * D);
    const float4* eh4 = (const float4*)(eh + (size_t)gw * D);
    float4 a = nh4[lane];
    float4 b = __ldcs(eh4 + lane);
    float4 v = make_float4(a.x + b.x, a.y + b.y, a.z + b.z, a.w + b.w);
    float* p = (float*)(g_agg4 + (size_t)dst * DV) + lane * 4;
    asm volatile("red.global.add.v4.f32 [%0], {%1, %2, %3, %4};"
                 :: "l"(p), "f"(v.x), "f"(v.y), "f"(v.z), "f"(v.w)
                 : "memory");
}

// ---------------------------------------------------------------------------
// K2: tensor-core MLP, NT=64 nodes/block, 8 warps (R6 proven form).
// Warp w: mh = w & 1 (32-row half), nq = w >> 1 (32-col quarter).
// ---------------------------------------------------------------------------
__global__ void k_mlp(const float* __restrict__ b1, const float* __restrict__ b2,
                      const float* __restrict__ lng, const float* __restrict__ lnb,
                      int N) {
    extern __shared__ char sb[];
    __nv_bfloat16* sHi = (__nv_bfloat16*)(sb);
    float*         sS  = (float*)(sb);
    float*         sPartS = (float*)(sb);
    float*         sPartQ = (float*)(sb + 4096);

    const int t    = threadIdx.x;
    const int lane = t & 31;
    const int w    = t >> 5;
    const int nodeBase = blockIdx.x * NT;

    // ---- load agg tile (64 nodes), split to bf16 hi/lo ----
    {
        int n  = t >> 2;             // 0..63
        int k0 = (t & 3) * 32;       // 0,32,64,96
        int gn = nodeBase + n;
        __nv_bfloat16* rowHi = sHi + n * PA;
        #pragma unroll
        for (int i = 0; i < 8; ++i) {
            float4 v = make_float4(0.f, 0.f, 0.f, 0.f);
            if (gn < N) v = g_agg4[(size_t)gn * DV + (k0 >> 2) + i];
            int kk = k0 + i * 4;
            float rx, ry, rz, rw;
            uint32_t h0 = bf2_hi(v.x, v.y, rx, ry);
            uint32_t h1 = bf2_hi(v.z, v.w, rz, rw);
            *(uint32_t*)((char*)(rowHi + kk))               = h0;
            *(uint32_t*)((char*)(rowHi + kk + 2))           = h1;
            *(uint32_t*)((char*)(rowHi + kk) + OFF_ALO)     = bf2(rx, ry);
            *(uint32_t*)((char*)(rowHi + kk + 2) + OFF_ALO) = bf2(rz, rw);
        }
    }
    __syncthreads();

    const int mh = w & 1;            // 32-row half
    const int nq = w >> 1;           // 32-col quarter
    const uint32_t aB0 = smem_u32(sHi + (mh * 32 + (lane & 15)) * PA) + (lane >> 4) * 16;
    const uint32_t aB1 = aB0 + 16 * PA * 2;   // +16 rows

    float acc[32];
    #pragma unroll
    for (int i = 0; i < 32; ++i) acc[i] = 0.f;

    // ---- layer 1: h1 = relu(agg @ W1 + b1) ----
    #pragma unroll
    for (int kt = 0; kt < 8; ++kt) {
        uint32_t a0h[4], a0l[4], a1h[4], a1l[4];
        ldsm_x4(a0h, aB0 + kt * 32);
        ldsm_x4(a0l, aB0 + OFF_ALO + kt * 32);
        ldsm_x4(a1h, aB1 + kt * 32);
        ldsm_x4(a1l, aB1 + OFF_ALO + kt * 32);
        #pragma unroll
        for (int s = 0; s < 4; ++s) {
            uint4 q = g_w1p[(kt * 16 + nq * 4 + s) * 32 + lane];
            mma16816(acc + 4 * s,      a0h, &q.x);
            mma16816(acc + 4 * s,      a0h, &q.z);
            mma16816(acc + 4 * s,      a0l, &q.x);
            mma16816(acc + 16 + 4 * s, a1h, &q.x);
            mma16816(acc + 16 + 4 * s, a1h, &q.z);
            mma16816(acc + 16 + 4 * s, a1l, &q.x);
        }
    }
    __syncthreads();                 // everyone done reading A -> overwrite with H
    #pragma unroll
    for (int m = 0; m < 2; ++m) {
        #pragma unroll
        for (int s = 0; s < 4; ++s) {
            int cb = nq * 32 + s * 8 + (lane & 3) * 2;
            int r0 = mh * 32 + m * 16 + (lane >> 2);
            float2 bb = *(const float2*)(b1 + cb);
            float v00 = fmaxf(acc[16*m + 4*s + 0] + bb.x, 0.f);
            float v01 = fmaxf(acc[16*m + 4*s + 1] + bb.y, 0.f);
            float v10 = fmaxf(acc[16*m + 4*s + 2] + bb.x, 0.f);
            float v11 = fmaxf(acc[16*m + 4*s + 3] + bb.y, 0.f);
            float rx, ry;
            char* p0 = (char*)(sHi + r0 * PA + cb);
            char* p1 = (char*)(sHi + (r0 + 8) * PA + cb);
            uint32_t h;
            h = bf2_hi(v00, v01, rx, ry);
            *(uint32_t*)p0 = h; *(uint32_t*)(p0 + OFF_ALO) = bf2(rx, ry);
            h = bf2_hi(v10, v11, rx, ry);
            *(uint32_t*)p1 = h; *(uint32_t*)(p1 + OFF_ALO) = bf2(rx, ry);
        }
    }
    __syncthreads();

    #pragma unroll
    for (int i = 0; i < 32; ++i) acc[i] = 0.f;

    // ---- layer 2: h2 = h1 @ W2 + b2 (H lives in the A region) ----
    #pragma unroll
    for (int kt = 0; kt < 8; ++kt) {
        uint32_t a0h[4], a0l[4], a1h[4], a1l[4];
        ldsm_x4(a0h, aB0 + kt * 32);
        ldsm_x4(a0l, aB0 + OFF_ALO + kt * 32);
        ldsm_x4(a1h, aB1 + kt * 32);
        ldsm_x4(a1l, aB1 + OFF_ALO + kt * 32);
        #pragma unroll
        for (int s = 0; s < 4; ++s) {
            uint4 q = g_w2p[(kt * 16 + nq * 4 + s) * 32 + lane];
            mma16816(acc + 4 * s,      a0h, &q.x);
            mma16816(acc + 4 * s,      a0h, &q.z);
            mma16816(acc + 4 * s,      a0l, &q.x);
            mma16816(acc + 16 + 4 * s, a1h, &q.x);
            mma16816(acc + 16 + 4 * s, a1h, &q.z);
            mma16816(acc + 16 + 4 * s, a1l, &q.x);
        }
    }
    __syncthreads();                 // H dead -> overwrite with sS
    #pragma unroll
    for (int m = 0; m < 2; ++m) {
        #pragma unroll
        for (int s = 0; s < 4; ++s) {
            int cb = nq * 32 + s * 8 + (lane & 3) * 2;
            int r0 = mh * 32 + m * 16 + (lane >> 2);
            float2 bb = *(const float2*)(b2 + cb);
            *(float2*)(sS + r0 * PS + cb)       = make_float2(acc[16*m + 4*s + 0] + bb.x,
                                                              acc[16*m + 4*s + 1] + bb.y);
            *(float2*)(sS + (r0 + 8) * PS + cb) = make_float2(acc[16*m + 4*s + 2] + bb.x,
                                                              acc[16*m + 4*s + 3] + bb.y);
        }
    }
    __syncthreads();

    // ---- LayerNorm per node (warp per node, 8 nodes/warp) + column partials ----
    float colS[4] = {0.f, 0.f, 0.f, 0.f};
    float colQ[4] = {0.f, 0.f, 0.f, 0.f};

    #pragma unroll
    for (int r = 0; r < 8; ++r) {
        int n  = w + r * 8;          // 0..63
        int gn = nodeBase + n;
        float v0 = sS[n * PS + lane];
        float v1 = sS[n * PS + lane + 32];
        float v2 = sS[n * PS + lane + 64];
        float v3 = sS[n * PS + lane + 96];
        float s = v0 + v1 + v2 + v3;
        float q = v0*v0 + v1*v1 + v2*v2 + v3*v3;
        #pragma unroll
        for (int o = 16; o; o >>= 1) {
            s += __shfl_xor_sync(0xFFFFFFFFu, s, o);
            q += __shfl_xor_sync(0xFFFFFFFFu, q, o);
        }
        float mu  = s * (1.f / 128.f);
        float var = q * (1.f / 128.f) - mu * mu;
        float inv = rsqrtf(var + EPS);
        if (gn < N) {
            float y0 = (v0 - mu) * inv * lng[lane]      + lnb[lane];
            float y1 = (v1 - mu) * inv * lng[lane + 32] + lnb[lane + 32];
            float y2 = (v2 - mu) * inv * lng[lane + 64] + lnb[lane + 64];
            float y3 = (v3 - mu) * inv * lng[lane + 96] + lnb[lane + 96];
            float* hp = (float*)(g_hln4 + (size_t)gn * DV);
            hp[lane]      = y0;
            hp[lane + 32] = y1;
            hp[lane + 64] = y2;
            hp[lane + 96] = y3;
            colS[0] += y0; colQ[0] += y0 * y0;
            colS[1] += y1; colQ[1] += y1 * y1;
            colS[2] += y2; colQ[2] += y2 * y2;
            colS[3] += y3; colQ[3] += y3 * y3;
        }
    }
    __syncthreads();                 // sS dead -> partials
    #pragma unroll
    for (int qq = 0; qq < 4; ++qq) {
        sPartS[w * D + lane + 32 * qq] = colS[qq];
        sPartQ[w * D + lane + 32 * qq] = colQ[qq];
    }
    __syncthreads();
    if (t < D) {
        float s = 0.f, q = 0.f;
        #pragma unroll
        for (int w8 = 0; w8 < 8; ++w8) {
            s += sPartS[w8 * D + t];
            q += sPartQ[w8 * D + t];
        }
        atomicAdd(&g_colsum[t], s);
        atomicAdd(&g_colsumsq[t], q);
    }
}

// ---------------------------------------------------------------------------
// K4: out = relu((hln - ms*gmu) * mul + gn_b) + node_hidden.
// 4 float4 per thread for ILP; stats finalized per block from L2 accumulators.
// ---------------------------------------------------------------------------
__global__ void k_final(const float* __restrict__ nh,
                        const float* __restrict__ gnw,
                        const float* __restrict__ gnb,
                        const float* __restrict__ gnms,
                        float invN,
                        float* __restrict__ out,
                        int total4) {
    __shared__ float sMul[D], sSub[D], sB[D];
    int t = threadIdx.x;
    if (t < D) {
        float gmu = g_colsum[t] * invN;
        float e2  = g_colsumsq[t] * invN;
        float ms  = gnms[t];
        float gvar = e2 - 2.f * ms * gmu * gmu + ms * ms * gmu * gmu;
        sMul[t] = rsqrtf(gvar + EPS) * gnw[t];
        sSub[t] = ms * gmu;
        sB[t]   = gnb[t];
    }
    __syncthreads();
    int base = blockIdx.x * 1024 + t;
    #pragma unroll
    for (int u = 0; u < 4; ++u) {
        int i = base + u * 256;
        if (i >= total4) break;
        int c4 = (i & (DV - 1)) * 4;
        float4 h = g_hln4[i];
        float4 x = ((const float4*)nh)[i];
        float4 o;
        o.x = fmaxf((h.x - sSub[c4 + 0]) * sMul[c4 + 0] + sB[c4 + 0], 0.f) + x.x;
        o.y = fmaxf((h.y - sSub[c4 + 1]) * sMul[c4 + 1] + sB[c4 + 1], 0.f) + x.y;
        o.z = fmaxf((h.z - sSub[c4 + 2]) * sMul[c4 + 2] + sB[c4 + 2], 0.f) + x.z;
        o.w = fmaxf((h.w - sSub[c4 + 3]) * sMul[c4 + 3] + sB[c4 + 3], 0.f) + x.w;
        ((float4*)out)[i] = o;
    }
}

// ---------------------------------------------------------------------------
extern "C" void kernel_launch(void* const* d_in, const int* in_sizes, int n_in,
                              void* d_out, int out_size) {
    const float* nh   = (const float*)d_in[0];
    const float* eh   = (const float*)d_in[1];
    const float* w1   = (const float*)d_in[2];
    const float* b1   = (const float*)d_in[3];
    const float* w2   = (const float*)d_in[4];
    const float* b2   = (const float*)d_in[5];
    const float* lng  = (const float*)d_in[6];
    const float* lnb  = (const float*)d_in[7];
    const float* gnw  = (const float*)d_in[8];
    const float* gnb  = (const float*)d_in[9];
    const float* gnms = (const float*)d_in[10];
    const int*   ei   = (const int*)d_in[11];

    int N = in_sizes[0] / D;
    int E = in_sizes[1] / D;
    int total4 = N * DV;

    cudaFuncSetAttribute(k_mlp, cudaFuncAttributeMaxDynamicSharedMemorySize, SMEM_TOTAL);

    k_pre<<<(total4 + 1023) / 1024, 256>>>(w1, w2, total4);
    k_scatter<<<(E + 7) / 8, 256>>>(nh, eh, ei, E);
    k_mlp<<<(N + NT - 1) / NT, 256, SMEM_TOTAL>>>(b1, b2, lng, lnb, N);
    k_final<<<(total4 + 1023) / 1024, 256>>>(nh, gnw, gnb, gnms, 1.f / (float)N,
                                             (float*)d_out, total4);
}

// round 11
// speedup vs baseline: 1.5147x; 1.0604x over previous
#include <cuda_runtime.h>
#include <cuda_fp16.h>
#include <cstdint>

#define D 128
#define DV 32          // D / 4 (float4)
#define EPS 1e-5f
#define NT 64          // nodes per MLP block
#define PA 136         // fp16 tile pitch (272B rows -> conflict-free LDSM)
#define PS 132         // f32 h2 tile pitch
#define MAXN 50000

// Device scratch (allocation-free rule: __device__ globals)
__device__ float4 g_agg4[(size_t)MAXN * DV];   // aggregated messages [N][D]
__device__ float4 g_hln4[(size_t)MAXN * DV];   // post-LayerNorm h    [N][D]
__device__ float  g_colsum[D];
__device__ float  g_colsumsq[D];
// Pre-packed fp16 weights (hi only) in B-fragment register order:
// [kt(8)][nsub(16)][lane(32)] -> uint2{b0,b1}
__device__ uint2  g_w1p[4096];
__device__ uint2  g_w2p[4096];

// SMEM layout for k_mlp (A region reused for H, then sS, then partials)
#define OFF_ALO 17408            // hi at 0, lo at 17408
#define SMEM_TOTAL 34816

// ---------------------------------------------------------------------------
// helpers
// ---------------------------------------------------------------------------
__device__ __forceinline__ uint32_t smem_u32(const void* p) {
    return (uint32_t)__cvta_generic_to_shared(p);
}

__device__ __forceinline__ void ldsm_x4(uint32_t* r, uint32_t addr) {
    asm volatile("ldmatrix.sync.aligned.m8n8.x4.shared.b16 {%0,%1,%2,%3}, [%4];"
                 : "=r"(r[0]), "=r"(r[1]), "=r"(r[2]), "=r"(r[3]) : "r"(addr));
}

__device__ __forceinline__ void mma_h(float* d, const uint32_t* a,
                                      const uint32_t* b) {
    asm volatile(
        "mma.sync.aligned.m16n8k16.row.col.f32.f16.f16.f32 "
        "{%0,%1,%2,%3}, {%4,%5,%6,%7}, {%8,%9}, {%0,%1,%2,%3};"
        : "+f"(d[0]), "+f"(d[1]), "+f"(d[2]), "+f"(d[3])
        : "r"(a[0]), "r"(a[1]), "r"(a[2]), "r"(a[3]), "r"(b[0]), "r"(b[1]));
}

// pack two floats into fp16x2 (hi parts); residuals returned via ra/rb
__device__ __forceinline__ uint32_t h2_hi(float a, float b, float& ra, float& rb) {
    __half ha = __float2half_rn(a);
    __half hb = __float2half_rn(b);
    ra = a - __half2float(ha);
    rb = b - __half2float(hb);
    __half2 h; h.x = ha; h.y = hb;
    return *(uint32_t*)&h;
}
__device__ __forceinline__ uint32_t h2(float a, float b) {
    __half2 h; h.x = __float2half_rn(a); h.y = __float2half_rn(b);
    return *(uint32_t*)&h;
}

// ---------------------------------------------------------------------------
// K0: zero agg (L2-warm for the scatter atomics) + stats, pack weights.
// 4 float4 per thread. grid = ceil(total4/1024); first 16 blocks pack W1/W2.
// ---------------------------------------------------------------------------
__global__ void k_pre(const float* __restrict__ w1, const float* __restrict__ w2,
                      int total4) {
    int idx = blockIdx.x * blockDim.x + threadIdx.x;
    int base = blockIdx.x * 1024 + threadIdx.x;
    #pragma unroll
    for (int u = 0; u < 4; ++u) {
        int i = base + u * 256;
        if (i < total4) g_agg4[i] = make_float4(0.f, 0.f, 0.f, 0.f);
    }
    if (idx < D) { g_colsum[idx] = 0.f; g_colsumsq[idx] = 0.f; }
    if (idx >= 4096) return;

    int lane = idx & 31;
    int nsub = (idx >> 5) & 15;
    int kt   = idx >> 9;
    int k0 = kt * 16 + (lane & 3) * 2;
    int n  = nsub * 8 + (lane >> 2);

    {
        uint2 q;
        q.x = h2(w1[(k0    ) * D + n], w1[(k0 + 1) * D + n]);
        q.y = h2(w1[(k0 + 8) * D + n], w1[(k0 + 9) * D + n]);
        g_w1p[idx] = q;
    }
    {
        uint2 q;
        q.x = h2(w2[(k0    ) * D + n], w2[(k0 + 1) * D + n]);
        q.y = h2(w2[(k0 + 8) * D + n], w2[(k0 + 9) * D + n]);
        g_w2p[idx] = q;
    }
}

// ---------------------------------------------------------------------------
// K1: scatter-add messages. eh streamed via __ldcs (read-once, evict-first);
// nh gather stays default-cached (hot 25.6MB table). edge_index is int32.
// ---------------------------------------------------------------------------
__global__ void k_scatter(const float* __restrict__ nh,
                          const float* __restrict__ eh,
                          const int* __restrict__ ei,
                          int E) {
    int gw   = (blockIdx.x * blockDim.x + threadIdx.x) >> 5;
    int lane = threadIdx.x & 31;
    if (gw >= E) return;
    int src = ei[gw];
    int dst = ei[E + gw];
    const float4* nh4 = (const float4*)(nh + (size_t)src * D);
    const float4* eh4 = (const float4*)(eh + (size_t)gw * D);
    float4 a = nh4[lane];
    float4 b = __ldcs(eh4 + lane);
    float4 v = make_float4(a.x + b.x, a.y + b.y, a.z + b.z, a.w + b.w);
    float* p = (float*)(g_agg4 + (size_t)dst * DV) + lane * 4;
    asm volatile("red.global.add.v4.f32 [%0], {%1, %2, %3, %4};"
                 :: "l"(p), "f"(v.x), "f"(v.y), "f"(v.z), "f"(v.w)
                 : "memory");
}

// ---------------------------------------------------------------------------
// K2: tensor-core MLP, NT=64 nodes/block, 8 warps.
// fp16 2-term split: a = ah + al (fp16 each), weights fp16 hi only.
// acc = ah*wh + al*wh = a*wh  (dropped term a*(w-wh) ~ 2^-12 relative).
// Warp w: mh = w & 1 (32-row half), nq = w >> 1 (32-col quarter).
// ---------------------------------------------------------------------------
__global__ void k_mlp(const float* __restrict__ b1, const float* __restrict__ b2,
                      const float* __restrict__ lng, const float* __restrict__ lnb,
                      int N) {
    extern __shared__ char sb[];
    __half* sHi = (__half*)(sb);
    float*  sS  = (float*)(sb);
    float*  sPartS = (float*)(sb);
    float*  sPartQ = (float*)(sb + 4096);

    const int t    = threadIdx.x;
    const int lane = t & 31;
    const int w    = t >> 5;
    const int nodeBase = blockIdx.x * NT;

    // ---- load agg tile (64 nodes), split to fp16 hi/lo ----
    {
        int n  = t >> 2;             // 0..63
        int k0 = (t & 3) * 32;       // 0,32,64,96
        int gn = nodeBase + n;
        __half* rowHi = sHi + n * PA;
        #pragma unroll
        for (int i = 0; i < 8; ++i) {
            float4 v = make_float4(0.f, 0.f, 0.f, 0.f);
            if (gn < N) v = g_agg4[(size_t)gn * DV + (k0 >> 2) + i];
            int kk = k0 + i * 4;
            float rx, ry, rz, rw;
            uint32_t h0 = h2_hi(v.x, v.y, rx, ry);
            uint32_t h1 = h2_hi(v.z, v.w, rz, rw);
            *(uint32_t*)((char*)(rowHi + kk))               = h0;
            *(uint32_t*)((char*)(rowHi + kk + 2))           = h1;
            *(uint32_t*)((char*)(rowHi + kk) + OFF_ALO)     = h2(rx, ry);
            *(uint32_t*)((char*)(rowHi + kk + 2) + OFF_ALO) = h2(rz, rw);
        }
    }
    __syncthreads();

    const int mh = w & 1;            // 32-row half
    const int nq = w >> 1;           // 32-col quarter
    const uint32_t aB0 = smem_u32(sHi + (mh * 32 + (lane & 15)) * PA) + (lane >> 4) * 16;
    const uint32_t aB1 = aB0 + 16 * PA * 2;   // +16 rows

    float acc[32];
    #pragma unroll
    for (int i = 0; i < 32; ++i) acc[i] = 0.f;

    // ---- layer 1: h1 = relu(agg @ W1 + b1) ----
    #pragma unroll
    for (int kt = 0; kt < 8; ++kt) {
        uint32_t a0h[4], a0l[4], a1h[4], a1l[4];
        ldsm_x4(a0h, aB0 + kt * 32);
        ldsm_x4(a0l, aB0 + OFF_ALO + kt * 32);
        ldsm_x4(a1h, aB1 + kt * 32);
        ldsm_x4(a1l, aB1 + OFF_ALO + kt * 32);
        #pragma unroll
        for (int s = 0; s < 4; ++s) {
            uint2 q = g_w1p[(kt * 16 + nq * 4 + s) * 32 + lane];
            mma_h(acc + 4 * s,      a0h, &q.x);
            mma_h(acc + 4 * s,      a0l, &q.x);
            mma_h(acc + 16 + 4 * s, a1h, &q.x);
            mma_h(acc + 16 + 4 * s, a1l, &q.x);
        }
    }
    __syncthreads();                 // everyone done reading A -> overwrite with H
    #pragma unroll
    for (int m = 0; m < 2; ++m) {
        #pragma unroll
        for (int s = 0; s < 4; ++s) {
            int cb = nq * 32 + s * 8 + (lane & 3) * 2;
            int r0 = mh * 32 + m * 16 + (lane >> 2);
            float2 bb = *(const float2*)(b1 + cb);
            float v00 = fmaxf(acc[16*m + 4*s + 0] + bb.x, 0.f);
            float v01 = fmaxf(acc[16*m + 4*s + 1] + bb.y, 0.f);
            float v10 = fmaxf(acc[16*m + 4*s + 2] + bb.x, 0.f);
            float v11 = fmaxf(acc[16*m + 4*s + 3] + bb.y, 0.f);
            float rx, ry;
            char* p0 = (char*)(sHi + r0 * PA + cb);
            char* p1 = (char*)(sHi + (r0 + 8) * PA + cb);
            uint32_t h;
            h = h2_hi(v00, v01, rx, ry);
            *(uint32_t*)p0 = h; *(uint32_t*)(p0 + OFF_ALO) = h2(rx, ry);
            h = h2_hi(v10, v11, rx, ry);
            *(uint32_t*)p1 = h; *(uint32_t*)(p1 + OFF_ALO) = h2(rx, ry);
        }
    }
    __syncthreads();

    #pragma unroll
    for (int i = 0; i < 32; ++i) acc[i] = 0.f;

    // ---- layer 2: h2 = h1 @ W2 + b2 (H lives in the A region) ----
    #pragma unroll
    for (int kt = 0; kt < 8; ++kt) {
        uint32_t a0h[4], a0l[4], a1h[4], a1l[4];
        ldsm_x4(a0h, aB0 + kt * 32);
        ldsm_x4(a0l, aB0 + OFF_ALO + kt * 32);
        ldsm_x4(a1h, aB1 + kt * 32);
        ldsm_x4(a1l, aB1 + OFF_ALO + kt * 32);
        #pragma unroll
        for (int s = 0; s < 4; ++s) {
            uint2 q = g_w2p[(kt * 16 + nq * 4 + s) * 32 + lane];
            mma_h(acc + 4 * s,      a0h, &q.x);
            mma_h(acc + 4 * s,      a0l, &q.x);
            mma_h(acc + 16 + 4 * s, a1h, &q.x);
            mma_h(acc + 16 + 4 * s, a1l, &q.x);
        }
    }
    __syncthreads();                 // H dead -> overwrite with sS
    #pragma unroll
    for (int m = 0; m < 2; ++m) {
        #pragma unroll
        for (int s = 0; s < 4; ++s) {
            int cb = nq * 32 + s * 8 + (lane & 3) * 2;
            int r0 = mh * 32 + m * 16 + (lane >> 2);
            float2 bb = *(const float2*)(b2 + cb);
            *(float2*)(sS + r0 * PS + cb)       = make_float2(acc[16*m + 4*s + 0] + bb.x,
                                                              acc[16*m + 4*s + 1] + bb.y);
            *(float2*)(sS + (r0 + 8) * PS + cb) = make_float2(acc[16*m + 4*s + 2] + bb.x,
                                                              acc[16*m + 4*s + 3] + bb.y);
        }
    }
    __syncthreads();

    // ---- LayerNorm per node (warp per node, 8 nodes/warp) + column partials ----
    float colS[4] = {0.f, 0.f, 0.f, 0.f};
    float colQ[4] = {0.f, 0.f, 0.f, 0.f};

    #pragma unroll
    for (int r = 0; r < 8; ++r) {
        int n  = w + r * 8;          // 0..63
        int gn = nodeBase + n;
        float v0 = sS[n * PS + lane];
        float v1 = sS[n * PS + lane + 32];
        float v2 = sS[n * PS + lane + 64];
        float v3 = sS[n * PS + lane + 96];
        float s = v0 + v1 + v2 + v3;
        float q = v0*v0 + v1*v1 + v2*v2 + v3*v3;
        #pragma unroll
        for (int o = 16; o; o >>= 1) {
            s += __shfl_xor_sync(0xFFFFFFFFu, s, o);
            q += __shfl_xor_sync(0xFFFFFFFFu, q, o);
        }
        float mu  = s * (1.f / 128.f);
        float var = q * (1.f / 128.f) - mu * mu;
        float inv = rsqrtf(var + EPS);
        if (gn < N) {
            float y0 = (v0 - mu) * inv * lng[lane]      + lnb[lane];
            float y1 = (v1 - mu) * inv * lng[lane + 32] + lnb[lane + 32];
            float y2 = (v2 - mu) * inv * lng[lane + 64] + lnb[lane + 64];
            float y3 = (v3 - mu) * inv * lng[lane + 96] + lnb[lane + 96];
            float* hp = (float*)(g_hln4 + (size_t)gn * DV);
            hp[lane]      = y0;
            hp[lane + 32] = y1;
            hp[lane + 64] = y2;
            hp[lane + 96] = y3;
            colS[0] += y0; colQ[0] += y0 * y0;
            colS[1] += y1; colQ[1] += y1 * y1;
            colS[2] += y2; colQ[2] += y2 * y2;
            colS[3] += y3; colQ[3] += y3 * y3;
        }
    }
    __syncthreads();                 // sS dead -> partials
    #pragma unroll
    for (int qq = 0; qq < 4; ++qq) {
        sPartS[w * D + lane + 32 * qq] = colS[qq];
        sPartQ[w * D + lane + 32 * qq] = colQ[qq];
    }
    __syncthreads();
    if (t < D) {
        float s = 0.f, q = 0.f;
        #pragma unroll
        for (int w8 = 0; w8 < 8; ++w8) {
            s += sPartS[w8 * D + t];
            q += sPartQ[w8 * D + t];
        }
        atomicAdd(&g_colsum[t], s);
        atomicAdd(&g_colsumsq[t], q);
    }
}

// ---------------------------------------------------------------------------
// K4: out = relu((hln - ms*gmu) * mul + gn_b) + node_hidden.
// 2 float4 per thread (best measured config); stats finalized per block.
// ---------------------------------------------------------------------------
__global__ void k_final(const float* __restrict__ nh,
                        const float* __restrict__ gnw,
                        const float* __restrict__ gnb,
                        const float* __restrict__ gnms,
                        float invN,
                        float* __restrict__ out,
                        int total4) {
    __shared__ float sMul[D], sSub[D], sB[D];
    int t = threadIdx.x;
    if (t < D) {
        float gmu = g_colsum[t] * invN;
        float e2  = g_colsumsq[t] * invN;
        float ms  = gnms[t];
        float gvar = e2 - 2.f * ms * gmu * gmu + ms * ms * gmu * gmu;
        sMul[t] = rsqrtf(gvar + EPS) * gnw[t];
        sSub[t] = ms * gmu;
        sB[t]   = gnb[t];
    }
    __syncthreads();
    int base = blockIdx.x * 512 + t;
    #pragma unroll
    for (int u = 0; u < 2; ++u) {
        int i = base + u * 256;
        if (i >= total4) break;
        int c4 = (i & (DV - 1)) * 4;
        float4 h = g_hln4[i];
        float4 x = ((const float4*)nh)[i];
        float4 o;
        o.x = fmaxf((h.x - sSub[c4 + 0]) * sMul[c4 + 0] + sB[c4 + 0], 0.f) + x.x;
        o.y = fmaxf((h.y - sSub[c4 + 1]) * sMul[c4 + 1] + sB[c4 + 1], 0.f) + x.y;
        o.z = fmaxf((h.z - sSub[c4 + 2]) * sMul[c4 + 2] + sB[c4 + 2], 0.f) + x.z;
        o.w = fmaxf((h.w - sSub[c4 + 3]) * sMul[c4 + 3] + sB[c4 + 3], 0.f) + x.w;
        ((float4*)out)[i] = o;
    }
}

// ---------------------------------------------------------------------------
extern "C" void kernel_launch(void* const* d_in, const int* in_sizes, int n_in,
                              void* d_out, int out_size) {
    const float* nh   = (const float*)d_in[0];
    const float* eh   = (const float*)d_in[1];
    const float* w1   = (const float*)d_in[2];
    const float* b1   = (const float*)d_in[3];
    const float* w2   = (const float*)d_in[4];
    const float* b2   = (const float*)d_in[5];
    const float* lng  = (const float*)d_in[6];
    const float* lnb  = (const float*)d_in[7];
    const float* gnw  = (const float*)d_in[8];
    const float* gnb  = (const float*)d_in[9];
    const float* gnms = (const float*)d_in[10];
    const int*   ei   = (const int*)d_in[11];

    int N = in_sizes[0] / D;
    int E = in_sizes[1] / D;
    int total4 = N * DV;

    cudaFuncSetAttribute(k_mlp, cudaFuncAttributeMaxDynamicSharedMemorySize, SMEM_TOTAL);

    k_pre<<<(total4 + 1023) / 1024, 256>>>(w1, w2, total4);
    k_scatter<<<(E + 7) / 8, 256>>>(nh, eh, ei, E);
    k_mlp<<<(N + NT - 1) / NT, 256, SMEM_TOTAL>>>(b1, b2, lng, lnb, N);
    k_final<<<(total4 + 511) / 512, 256>>>(nh, gnw, gnb, gnms, 1.f / (float)N,
                                           (float*)d_out, total4);
}

// round 12
// speedup vs baseline: 1.5347x; 1.0132x over previous
#include <cuda_runtime.h>
#include <cuda_fp16.h>
#include <cstdint>

#define D 128
#define DV 32          // D / 4 (float4)
#define EPS 1e-5f
#define NT 64          // nodes per MLP block
#define PA 136         // fp16 tile pitch (272B rows -> conflict-free LDSM)
#define PS 132         // f32 h2 tile pitch
#define MAXN 50000

// Device scratch (allocation-free rule: __device__ globals)
__device__ float4 g_agg4[(size_t)MAXN * DV];   // aggregated messages [N][D]
__device__ float4 g_hln4[(size_t)MAXN * DV];   // post-LayerNorm h    [N][D]
__device__ float  g_colsum[D];
__device__ float  g_colsumsq[D];
// Pre-packed fp16 weights in B-fragment register order:
// [kt(8)][nsub(16)][lane(32)] -> uint2{b0,b1}
__device__ uint2  g_w1p[4096];
__device__ uint2  g_w2p[4096];

// SMEM for k_mlp: fp16 tile 64 x PA (17408 B); sS (64 x PS f32 = 33792 B)
// overlays it post-GEMM, so total is sized for sS.
#define SMEM_TOTAL 34816

// ---------------------------------------------------------------------------
// helpers
// ---------------------------------------------------------------------------
__device__ __forceinline__ uint32_t smem_u32(const void* p) {
    return (uint32_t)__cvta_generic_to_shared(p);
}

__device__ __forceinline__ void ldsm_x4(uint32_t* r, uint32_t addr) {
    asm volatile("ldmatrix.sync.aligned.m8n8.x4.shared.b16 {%0,%1,%2,%3}, [%4];"
                 : "=r"(r[0]), "=r"(r[1]), "=r"(r[2]), "=r"(r[3]) : "r"(addr));
}

__device__ __forceinline__ void mma_h(float* d, const uint32_t* a,
                                      const uint32_t* b) {
    asm volatile(
        "mma.sync.aligned.m16n8k16.row.col.f32.f16.f16.f32 "
        "{%0,%1,%2,%3}, {%4,%5,%6,%7}, {%8,%9}, {%0,%1,%2,%3};"
        : "+f"(d[0]), "+f"(d[1]), "+f"(d[2]), "+f"(d[3])
        : "r"(a[0]), "r"(a[1]), "r"(a[2]), "r"(a[3]), "r"(b[0]), "r"(b[1]));
}

__device__ __forceinline__ uint32_t h2(float a, float b) {
    __half2 h; h.x = __float2half_rn(a); h.y = __float2half_rn(b);
    return *(uint32_t*)&h;
}

// ---------------------------------------------------------------------------
// K0: zero agg (L2-warm for the scatter atomics) + stats, pack weights.
// 4 float4 per thread. grid = ceil(total4/1024); first 16 blocks pack W1/W2.
// ---------------------------------------------------------------------------
__global__ void k_pre(const float* __restrict__ w1, const float* __restrict__ w2,
                      int total4) {
    int idx = blockIdx.x * blockDim.x + threadIdx.x;
    int base = blockIdx.x * 1024 + threadIdx.x;
    #pragma unroll
    for (int u = 0; u < 4; ++u) {
        int i = base + u * 256;
        if (i < total4) g_agg4[i] = make_float4(0.f, 0.f, 0.f, 0.f);
    }
    if (idx < D) { g_colsum[idx] = 0.f; g_colsumsq[idx] = 0.f; }
    if (idx >= 4096) return;

    int lane = idx & 31;
    int nsub = (idx >> 5) & 15;
    int kt   = idx >> 9;
    int k0 = kt * 16 + (lane & 3) * 2;
    int n  = nsub * 8 + (lane >> 2);

    {
        uint2 q;
        q.x = h2(w1[(k0    ) * D + n], w1[(k0 + 1) * D + n]);
        q.y = h2(w1[(k0 + 8) * D + n], w1[(k0 + 9) * D + n]);
        g_w1p[idx] = q;
    }
    {
        uint2 q;
        q.x = h2(w2[(k0    ) * D + n], w2[(k0 + 1) * D + n]);
        q.y = h2(w2[(k0 + 8) * D + n], w2[(k0 + 9) * D + n]);
        g_w2p[idx] = q;
    }
}

// ---------------------------------------------------------------------------
// K1: scatter-add messages. eh streamed via __ldcs (read-once, evict-first);
// nh gather stays default-cached (hot 25.6MB table). edge_index is int32.
// ---------------------------------------------------------------------------
__global__ void k_scatter(const float* __restrict__ nh,
                          const float* __restrict__ eh,
                          const int* __restrict__ ei,
                          int E) {
    int gw   = (blockIdx.x * blockDim.x + threadIdx.x) >> 5;
    int lane = threadIdx.x & 31;
    if (gw >= E) return;
    int src = ei[gw];
    int dst = ei[E + gw];
    const float4* nh4 = (const float4*)(nh + (size_t)src * D);
    const float4* eh4 = (const float4*)(eh + (size_t)gw * D);
    float4 a = nh4[lane];
    float4 b = __ldcs(eh4 + lane);
    float4 v = make_float4(a.x + b.x, a.y + b.y, a.z + b.z, a.w + b.w);
    float* p = (float*)(g_agg4 + (size_t)dst * DV) + lane * 4;
    asm volatile("red.global.add.v4.f32 [%0], {%1, %2, %3, %4};"
                 :: "l"(p), "f"(v.x), "f"(v.y), "f"(v.z), "f"(v.w)
                 : "memory");
}

// ---------------------------------------------------------------------------
// K2: tensor-core MLP, NT=64 nodes/block, 8 warps.
// Pure fp16 operands (f32 accumulate): acc = ah*wh; dropped terms ~2^-11 rel.
// Warp w: mh = w & 1 (32-row half), nq = w >> 1 (32-col quarter).
// ---------------------------------------------------------------------------
__global__ void k_mlp(const float* __restrict__ b1, const float* __restrict__ b2,
                      const float* __restrict__ lng, const float* __restrict__ lnb,
                      int N) {
    extern __shared__ char sb[];
    __half* sHi = (__half*)(sb);
    float*  sS  = (float*)(sb);
    float*  sPartS = (float*)(sb);
    float*  sPartQ = (float*)(sb + 4096);

    const int t    = threadIdx.x;
    const int lane = t & 31;
    const int w    = t >> 5;
    const int nodeBase = blockIdx.x * NT;

    // ---- load agg tile (64 nodes) as fp16 ----
    {
        int n  = t >> 2;             // 0..63
        int k0 = (t & 3) * 32;       // 0,32,64,96
        int gn = nodeBase + n;
        __half* rowHi = sHi + n * PA;
        #pragma unroll
        for (int i = 0; i < 8; ++i) {
            float4 v = make_float4(0.f, 0.f, 0.f, 0.f);
            if (gn < N) v = g_agg4[(size_t)gn * DV + (k0 >> 2) + i];
            int kk = k0 + i * 4;
            *(uint32_t*)((char*)(rowHi + kk))     = h2(v.x, v.y);
            *(uint32_t*)((char*)(rowHi + kk + 2)) = h2(v.z, v.w);
        }
    }
    __syncthreads();

    const int mh = w & 1;            // 32-row half
    const int nq = w >> 1;           // 32-col quarter
    const uint32_t aB0 = smem_u32(sHi + (mh * 32 + (lane & 15)) * PA) + (lane >> 4) * 16;
    const uint32_t aB1 = aB0 + 16 * PA * 2;   // +16 rows

    float acc[32];
    #pragma unroll
    for (int i = 0; i < 32; ++i) acc[i] = 0.f;

    // ---- layer 1: h1 = relu(agg @ W1 + b1) ----
    #pragma unroll
    for (int kt = 0; kt < 8; ++kt) {
        uint32_t a0h[4], a1h[4];
        ldsm_x4(a0h, aB0 + kt * 32);
        ldsm_x4(a1h, aB1 + kt * 32);
        #pragma unroll
        for (int s = 0; s < 4; ++s) {
            uint2 q = g_w1p[(kt * 16 + nq * 4 + s) * 32 + lane];
            mma_h(acc + 4 * s,      a0h, &q.x);
            mma_h(acc + 16 + 4 * s, a1h, &q.x);
        }
    }
    __syncthreads();                 // everyone done reading A -> overwrite with H
    #pragma unroll
    for (int m = 0; m < 2; ++m) {
        #pragma unroll
        for (int s = 0; s < 4; ++s) {
            int cb = nq * 32 + s * 8 + (lane & 3) * 2;
            int r0 = mh * 32 + m * 16 + (lane >> 2);
            float2 bb = *(const float2*)(b1 + cb);
            float v00 = fmaxf(acc[16*m + 4*s + 0] + bb.x, 0.f);
            float v01 = fmaxf(acc[16*m + 4*s + 1] + bb.y, 0.f);
            float v10 = fmaxf(acc[16*m + 4*s + 2] + bb.x, 0.f);
            float v11 = fmaxf(acc[16*m + 4*s + 3] + bb.y, 0.f);
            *(uint32_t*)((char*)(sHi + r0 * PA + cb))       = h2(v00, v01);
            *(uint32_t*)((char*)(sHi + (r0 + 8) * PA + cb)) = h2(v10, v11);
        }
    }
    __syncthreads();

    #pragma unroll
    for (int i = 0; i < 32; ++i) acc[i] = 0.f;

    // ---- layer 2: h2 = h1 @ W2 + b2 (H lives in the A region) ----
    #pragma unroll
    for (int kt = 0; kt < 8; ++kt) {
        uint32_t a0h[4], a1h[4];
        ldsm_x4(a0h, aB0 + kt * 32);
        ldsm_x4(a1h, aB1 + kt * 32);
        #pragma unroll
        for (int s = 0; s < 4; ++s) {
            uint2 q = g_w2p[(kt * 16 + nq * 4 + s) * 32 + lane];
            mma_h(acc + 4 * s,      a0h, &q.x);
            mma_h(acc + 16 + 4 * s, a1h, &q.x);
        }
    }
    __syncthreads();                 // H dead -> overwrite with sS
    #pragma unroll
    for (int m = 0; m < 2; ++m) {
        #pragma unroll
        for (int s = 0; s < 4; ++s) {
            int cb = nq * 32 + s * 8 + (lane & 3) * 2;
            int r0 = mh * 32 + m * 16 + (lane >> 2);
            float2 bb = *(const float2*)(b2 + cb);
            *(float2*)(sS + r0 * PS + cb)       = make_float2(acc[16*m + 4*s + 0] + bb.x,
                                                              acc[16*m + 4*s + 1] + bb.y);
            *(float2*)(sS + (r0 + 8) * PS + cb) = make_float2(acc[16*m + 4*s + 2] + bb.x,
                                                              acc[16*m + 4*s + 3] + bb.y);
        }
    }
    __syncthreads();

    // ---- LayerNorm per node (warp per node, 8 nodes/warp) + column partials ----
    float colS[4] = {0.f, 0.f, 0.f, 0.f};
    float colQ[4] = {0.f, 0.f, 0.f, 0.f};

    #pragma unroll
    for (int r = 0; r < 8; ++r) {
        int n  = w + r * 8;          // 0..63
        int gn = nodeBase + n;
        float v0 = sS[n * PS + lane];
        float v1 = sS[n * PS + lane + 32];
        float v2 = sS[n * PS + lane + 64];
        float v3 = sS[n * PS + lane + 96];
        float s = v0 + v1 + v2 + v3;
        float q = v0*v0 + v1*v1 + v2*v2 + v3*v3;
        #pragma unroll
        for (int o = 16; o; o >>= 1) {
            s += __shfl_xor_sync(0xFFFFFFFFu, s, o);
            q += __shfl_xor_sync(0xFFFFFFFFu, q, o);
        }
        float mu  = s * (1.f / 128.f);
        float var = q * (1.f / 128.f) - mu * mu;
        float inv = rsqrtf(var + EPS);
        if (gn < N) {
            float y0 = (v0 - mu) * inv * lng[lane]      + lnb[lane];
            float y1 = (v1 - mu) * inv * lng[lane + 32] + lnb[lane + 32];
            float y2 = (v2 - mu) * inv * lng[lane + 64] + lnb[lane + 64];
            float y3 = (v3 - mu) * inv * lng[lane + 96] + lnb[lane + 96];
            float* hp = (float*)(g_hln4 + (size_t)gn * DV);
            hp[lane]      = y0;
            hp[lane + 32] = y1;
            hp[lane + 64] = y2;
            hp[lane + 96] = y3;
            colS[0] += y0; colQ[0] += y0 * y0;
            colS[1] += y1; colQ[1] += y1 * y1;
            colS[2] += y2; colQ[2] += y2 * y2;
            colS[3] += y3; colQ[3] += y3 * y3;
        }
    }
    __syncthreads();                 // sS dead -> partials
    #pragma unroll
    for (int qq = 0; qq < 4; ++qq) {
        sPartS[w * D + lane + 32 * qq] = colS[qq];
        sPartQ[w * D + lane + 32 * qq] = colQ[qq];
    }
    __syncthreads();
    if (t < D) {
        float s = 0.f, q = 0.f;
        #pragma unroll
        for (int w8 = 0; w8 < 8; ++w8) {
            s += sPartS[w8 * D + t];
            q += sPartQ[w8 * D + t];
        }
        atomicAdd(&g_colsum[t], s);
        atomicAdd(&g_colsumsq[t], q);
    }
}

// ---------------------------------------------------------------------------
// K4: out = relu((hln - ms*gmu) * mul + gn_b) + node_hidden.
// 2 float4 per thread; stats finalized per block from L2 accumulators.
// ---------------------------------------------------------------------------
__global__ void k_final(const float* __restrict__ nh,
                        const float* __restrict__ gnw,
                        const float* __restrict__ gnb,
                        const float* __restrict__ gnms,
                        float invN,
                        float* __restrict__ out,
                        int total4) {
    __shared__ float sMul[D], sSub[D], sB[D];
    int t = threadIdx.x;
    if (t < D) {
        float gmu = g_colsum[t] * invN;
        float e2  = g_colsumsq[t] * invN;
        float ms  = gnms[t];
        float gvar = e2 - 2.f * ms * gmu * gmu + ms * ms * gmu * gmu;
        sMul[t] = rsqrtf(gvar + EPS) * gnw[t];
        sSub[t] = ms * gmu;
        sB[t]   = gnb[t];
    }
    __syncthreads();
    int base = blockIdx.x * 512 + t;
    #pragma unroll
    for (int u = 0; u < 2; ++u) {
        int i = base + u * 256;
        if (i >= total4) break;
        int c4 = (i & (DV - 1)) * 4;
        float4 h = g_hln4[i];
        float4 x = ((const float4*)nh)[i];
        float4 o;
        o.x = fmaxf((h.x - sSub[c4 + 0]) * sMul[c4 + 0] + sB[c4 + 0], 0.f) + x.x;
        o.y = fmaxf((h.y - sSub[c4 + 1]) * sMul[c4 + 1] + sB[c4 + 1], 0.f) + x.y;
        o.z = fmaxf((h.z - sSub[c4 + 2]) * sMul[c4 + 2] + sB[c4 + 2], 0.f) + x.z;
        o.w = fmaxf((h.w - sSub[c4 + 3]) * sMul[c4 + 3] + sB[c4 + 3], 0.f) + x.w;
        ((float4*)out)[i] = o;
    }
}

// ---------------------------------------------------------------------------
extern "C" void kernel_launch(void* const* d_in, const int* in_sizes, int n_in,
                              void* d_out, int out_size) {
    const float* nh   = (const float*)d_in[0];
    const float* eh   = (const float*)d_in[1];
    const float* w1   = (const float*)d_in[2];
    const float* b1   = (const float*)d_in[3];
    const float* w2   = (const float*)d_in[4];
    const float* b2   = (const float*)d_in[5];
    const float* lng  = (const float*)d_in[6];
    const float* lnb  = (const float*)d_in[7];
    const float* gnw  = (const float*)d_in[8];
    const float* gnb  = (const float*)d_in[9];
    const float* gnms = (const float*)d_in[10];
    const int*   ei   = (const int*)d_in[11];

    int N = in_sizes[0] / D;
    int E = in_sizes[1] / D;
    int total4 = N * DV;

    cudaFuncSetAttribute(k_mlp, cudaFuncAttributeMaxDynamicSharedMemorySize, SMEM_TOTAL);

    k_pre<<<(total4 + 1023) / 1024, 256>>>(w1, w2, total4);
    k_scatter<<<(E + 7) / 8, 256>>>(nh, eh, ei, E);
    k_mlp<<<(N + NT - 1) / NT, 256, SMEM_TOTAL>>>(b1, b2, lng, lnb, N);
    k_final<<<(total4 + 511) / 512, 256>>>(nh, gnw, gnb, gnms, 1.f / (float)N,
                                           (float*)d_out, total4);
}